// round 1
// baseline (speedup 1.0000x reference)
#include <cuda_runtime.h>
#include <math.h>

#define BB 8
#define LL 2048
#define DD 512
#define BL (BB*LL)

// Scratch (static device allocations — allowed)
__device__ float g_qp[BL*DD];
__device__ float g_kp[BL*DD];
__device__ float g_vp[BL*DD];
__device__ float g_S[(size_t)BB*LL*LL];      // 134 MB score/P matrix
__device__ float g_cmax[BL];
__device__ float g_crcpz[BL];
__device__ float g_pm[8*BL];
__device__ float g_pz[8*BL];

// ---------------------------------------------------------------------------
// SGEMM NT: C[m,n] = sum_k A[m,k]*B[n,k] (+bias[n])   (both operands K-major)
// 128x128 block, BK=16, 8x8 per thread, 256 threads.
// ---------------------------------------------------------------------------
__global__ void __launch_bounds__(256) sgemm_nt(
    const float* __restrict__ A, const float* __restrict__ Bm,
    const float* __restrict__ bias, float* __restrict__ C,
    int M, int N, int K, size_t sA, size_t sB, size_t sC)
{
    constexpr int BM=128, BN=128, BK=16, TM=8, TN=8;
    __shared__ float As[BK][BM];
    __shared__ float Bs[BK][BN];
    const int tid = threadIdx.x;
    const int tx = tid & 15, ty = tid >> 4;
    const int m0 = blockIdx.y * BM, n0 = blockIdx.x * BN;
    A  += (size_t)blockIdx.z * sA;
    Bm += (size_t)blockIdx.z * sB;
    C  += (size_t)blockIdx.z * sC;

    float acc[TM][TN] = {};
    for (int k0 = 0; k0 < K; k0 += BK) {
        #pragma unroll
        for (int l = 0; l < 2; l++) {
            int idx = tid + l*256;          // 0..511
            int row = idx >> 2;             // BK/4 = 4 float4 per row
            int c4  = idx & 3;
            float4 v = *reinterpret_cast<const float4*>(&A[(size_t)(m0+row)*K + k0 + c4*4]);
            As[c4*4+0][row] = v.x; As[c4*4+1][row] = v.y;
            As[c4*4+2][row] = v.z; As[c4*4+3][row] = v.w;
        }
        #pragma unroll
        for (int l = 0; l < 2; l++) {
            int idx = tid + l*256;
            int row = idx >> 2;
            int c4  = idx & 3;
            float4 v = *reinterpret_cast<const float4*>(&Bm[(size_t)(n0+row)*K + k0 + c4*4]);
            Bs[c4*4+0][row] = v.x; Bs[c4*4+1][row] = v.y;
            Bs[c4*4+2][row] = v.z; Bs[c4*4+3][row] = v.w;
        }
        __syncthreads();
        #pragma unroll
        for (int k = 0; k < BK; k++) {
            float a[TM], b[TN];
            #pragma unroll
            for (int i = 0; i < TM; i++) a[i] = As[k][ty*TM+i];
            #pragma unroll
            for (int j = 0; j < TN; j++) b[j] = Bs[k][tx*TN+j];
            #pragma unroll
            for (int i = 0; i < TM; i++)
                #pragma unroll
                for (int j = 0; j < TN; j++)
                    acc[i][j] = fmaf(a[i], b[j], acc[i][j]);
        }
        __syncthreads();
    }
    #pragma unroll
    for (int i = 0; i < TM; i++) {
        int m = m0 + ty*TM + i;
        #pragma unroll
        for (int j = 0; j < TN; j += 4) {
            int n = n0 + tx*TN + j;
            float4 v;
            v.x = acc[i][j+0]; v.y = acc[i][j+1];
            v.z = acc[i][j+2]; v.w = acc[i][j+3];
            if (bias) {
                v.x += bias[n+0]; v.y += bias[n+1];
                v.z += bias[n+2]; v.w += bias[n+3];
            }
            *reinterpret_cast<float4*>(&C[(size_t)m*N + n]) = v;
        }
    }
}

// ---------------------------------------------------------------------------
// SGEMM NN: C[m,n] = sum_k A[m,k]*B[k,n]   (B row-major KxN)
// ---------------------------------------------------------------------------
__global__ void __launch_bounds__(256) sgemm_nn(
    const float* __restrict__ A, const float* __restrict__ Bm,
    float* __restrict__ C,
    int M, int N, int K, size_t sA, size_t sB, size_t sC)
{
    constexpr int BM=128, BN=128, BK=16, TM=8, TN=8;
    __shared__ float As[BK][BM];
    __shared__ float Bs[BK][BN];
    const int tid = threadIdx.x;
    const int tx = tid & 15, ty = tid >> 4;
    const int m0 = blockIdx.y * BM, n0 = blockIdx.x * BN;
    A  += (size_t)blockIdx.z * sA;
    Bm += (size_t)blockIdx.z * sB;
    C  += (size_t)blockIdx.z * sC;

    float acc[TM][TN] = {};
    for (int k0 = 0; k0 < K; k0 += BK) {
        #pragma unroll
        for (int l = 0; l < 2; l++) {
            int idx = tid + l*256;
            int row = idx >> 2;
            int c4  = idx & 3;
            float4 v = *reinterpret_cast<const float4*>(&A[(size_t)(m0+row)*K + k0 + c4*4]);
            As[c4*4+0][row] = v.x; As[c4*4+1][row] = v.y;
            As[c4*4+2][row] = v.z; As[c4*4+3][row] = v.w;
        }
        #pragma unroll
        for (int l = 0; l < 2; l++) {
            int idx = tid + l*256;          // 0..511
            int row = idx >> 5;             // BN/4 = 32 float4 per row -> 16 rows
            int c4  = idx & 31;
            float4 v = *reinterpret_cast<const float4*>(&Bm[(size_t)(k0+row)*N + n0 + c4*4]);
            *reinterpret_cast<float4*>(&Bs[row][c4*4]) = v;
        }
        __syncthreads();
        #pragma unroll
        for (int k = 0; k < BK; k++) {
            float a[TM], b[TN];
            #pragma unroll
            for (int i = 0; i < TM; i++) a[i] = As[k][ty*TM+i];
            #pragma unroll
            for (int j = 0; j < TN; j++) b[j] = Bs[k][tx*TN+j];
            #pragma unroll
            for (int i = 0; i < TM; i++)
                #pragma unroll
                for (int j = 0; j < TN; j++)
                    acc[i][j] = fmaf(a[i], b[j], acc[i][j]);
        }
        __syncthreads();
    }
    #pragma unroll
    for (int i = 0; i < TM; i++) {
        int m = m0 + ty*TM + i;
        #pragma unroll
        for (int j = 0; j < TN; j += 4) {
            int n = n0 + tx*TN + j;
            float4 v;
            v.x = acc[i][j+0]; v.y = acc[i][j+1];
            v.z = acc[i][j+2]; v.w = acc[i][j+3];
            *reinterpret_cast<float4*>(&C[(size_t)m*N + n]) = v;
        }
    }
}

// ---------------------------------------------------------------------------
// Column softmax stats (softmax over axis=1 == over rows i, per column j).
// Pass 1: partial online (max, sum) over a row-slice. 8 slices per batch.
// ---------------------------------------------------------------------------
__global__ void __launch_bounds__(256) colstats_partial()
{
    const int b     = blockIdx.z;
    const int slice = blockIdx.y;                 // 0..7
    const int j     = blockIdx.x*256 + threadIdx.x;
    const float* Sb = g_S + (size_t)b*LL*LL + (size_t)slice*(LL/8)*LL + j;
    float m = -INFINITY, z = 0.f;
    #pragma unroll 4
    for (int i = 0; i < LL/8; i++) {
        float s = Sb[(size_t)i*LL];
        if (s > m) { z = z*expf(m - s) + 1.f; m = s; }
        else       { z += expf(s - m); }
    }
    const int out = slice*BL + b*LL + j;
    g_pm[out] = m;
    g_pz[out] = z;
}

__global__ void __launch_bounds__(256) colstats_combine()
{
    const int c = blockIdx.x*256 + threadIdx.x;   // 0..BL-1
    float m = -INFINITY, z = 0.f;
    #pragma unroll
    for (int s = 0; s < 8; s++) {
        float mm = g_pm[s*BL + c];
        float zz = g_pz[s*BL + c];
        if (mm > m) { z = z*expf(m - mm) + zz; m = mm; }
        else        { z += zz*expf(mm - m); }
    }
    g_cmax[c]  = m;
    g_crcpz[c] = 1.f / z;
}

// P[b,i,j] = exp(S - cmax[b,j]) * crcpz[b,j], in place on S (float4 vectorized)
__global__ void __launch_bounds__(256) pnorm()
{
    size_t i4 = (size_t)blockIdx.x*256 + threadIdx.x;  // float4 index
    size_t e  = i4 * 4;
    int b = (int)(e >> 22);            // / (LL*LL)
    int j = (int)(e & (LL-1));
    float4 s = reinterpret_cast<float4*>(g_S)[i4];
    float4 m4 = *reinterpret_cast<const float4*>(&g_cmax[b*LL + j]);
    float4 z4 = *reinterpret_cast<const float4*>(&g_crcpz[b*LL + j]);
    s.x = expf(s.x - m4.x) * z4.x;
    s.y = expf(s.y - m4.y) * z4.y;
    s.z = expf(s.z - m4.z) * z4.z;
    s.w = expf(s.w - m4.w) * z4.w;
    reinterpret_cast<float4*>(g_S)[i4] = s;
}

extern "C" void kernel_launch(void* const* d_in, const int* in_sizes, int n_in,
                              void* d_out, int out_size)
{
    const float* q  = (const float*)d_in[0];
    const float* k  = (const float*)d_in[1];
    const float* v  = (const float*)d_in[2];
    const float* Wq = (const float*)d_in[3];
    const float* bq = (const float*)d_in[4];
    const float* Wk = (const float*)d_in[5];
    const float* bk = (const float*)d_in[6];
    const float* Wv = (const float*)d_in[7];
    const float* bv = (const float*)d_in[8];
    float* out = (float*)d_out;

    float *qp, *kp, *vp, *S;
    cudaGetSymbolAddress((void**)&qp, g_qp);
    cudaGetSymbolAddress((void**)&kp, g_kp);
    cudaGetSymbolAddress((void**)&vp, g_vp);
    cudaGetSymbolAddress((void**)&S,  g_S);

    // 1-3) Projections: (BL x D) = (BL x D) @ (D x D)^T + bias
    {
        dim3 grid(DD/128, BL/128, 1);
        sgemm_nt<<<grid, 256>>>(q, Wq, bq, qp, BL, DD, DD, 0, 0, 0);
        sgemm_nt<<<grid, 256>>>(k, Wk, bk, kp, BL, DD, DD, 0, 0, 0);
        sgemm_nt<<<grid, 256>>>(v, Wv, bv, vp, BL, DD, DD, 0, 0, 0);
    }

    // 4) S[b] = qp[b] @ kp[b]^T  (batched, M=N=L, K=D)
    {
        dim3 grid(LL/128, LL/128, BB);
        sgemm_nt<<<grid, 256>>>(qp, kp, nullptr, S, LL, LL, DD,
                                (size_t)LL*DD, (size_t)LL*DD, (size_t)LL*LL);
    }

    // 5) column softmax stats (over axis=1)
    {
        dim3 grid(LL/256, 8, BB);
        colstats_partial<<<grid, 256>>>();
        colstats_combine<<<BL/256, 256>>>();
    }

    // 6) P = exp(S - cmax) * rcpz, in place
    {
        size_t n4 = (size_t)BB*LL*LL/4;
        pnorm<<<(unsigned)(n4/256), 256>>>();
    }

    // 7) out[b] = P[b] @ vp[b]  (batched NN, M=L, N=D, K=L)
    {
        dim3 grid(DD/128, LL/128, BB);
        sgemm_nn<<<grid, 256>>>(S, vp, out, LL, DD, LL,
                                (size_t)LL*LL, (size_t)LL*DD, (size_t)LL*DD);
    }
}

// round 3
// speedup vs baseline: 2.4790x; 2.4790x over previous
#include <cuda_runtime.h>
#include <cuda_bf16.h>
#include <cstdint>
#include <math.h>

#define BB 8
#define LL 2048
#define DD 512
#define BL (BB*LL)

// ---------------------------------------------------------------------------
// Device scratch (static allocations — allowed)
// ---------------------------------------------------------------------------
__device__ __align__(256) float g_S[(size_t)BB*LL*LL];
__device__ __align__(256) __nv_bfloat16 g_Ph[(size_t)BB*LL*LL];
__device__ __align__(256) __nv_bfloat16 g_Pl[(size_t)BB*LL*LL];
__device__ __align__(256) __nv_bfloat16 g_qh[BL*DD], g_ql[BL*DD];
__device__ __align__(256) __nv_bfloat16 g_kh[BL*DD], g_kl[BL*DD];
__device__ __align__(256) __nv_bfloat16 g_vh[BL*DD], g_vl[BL*DD];
__device__ __align__(256) __nv_bfloat16 g_Wqh[DD*DD], g_Wql[DD*DD];
__device__ __align__(256) __nv_bfloat16 g_Wkh[DD*DD], g_Wkl[DD*DD];
__device__ __align__(256) __nv_bfloat16 g_Wvh[DD*DD], g_Wvl[DD*DD];
__device__ __align__(256) __nv_bfloat16 g_qph[BL*DD], g_qpl[BL*DD];
__device__ __align__(256) __nv_bfloat16 g_kph[BL*DD], g_kpl[BL*DD];
__device__ __align__(256) __nv_bfloat16 g_vpTh[BL*DD], g_vpTl[BL*DD]; // [B][D][L]
__device__ __align__(256) float g_cmax[BL];
__device__ __align__(256) float g_crcpz[BL];
__device__ __align__(256) float g_pm[8*BL];
__device__ __align__(256) float g_pz[8*BL];

// ---------------------------------------------------------------------------
// Portable PTX helpers (sm_80+ only — no 'a'-suffix features)
// ---------------------------------------------------------------------------
__device__ __forceinline__ uint32_t smem_u32(const void* p) {
    uint32_t a;
    asm("{ .reg .u64 t; cvta.to.shared.u64 t, %1; cvt.u32.u64 %0, t; }"
        : "=r"(a) : "l"(p));
    return a;
}

#define CP16(dst, src) \
    asm volatile("cp.async.cg.shared.global [%0], [%1], 16;" \
                 :: "r"(dst), "l"(src) : "memory")

#define CP_COMMIT() asm volatile("cp.async.commit_group;" ::: "memory")
#define CP_WAIT1()  asm volatile("cp.async.wait_group 1;" ::: "memory")

#define LDSM4(r0, r1, r2, r3, addr) \
    asm volatile("ldmatrix.sync.aligned.m8n8.x4.shared.b16 {%0,%1,%2,%3}, [%4];" \
                 : "=r"(r0), "=r"(r1), "=r"(r2), "=r"(r3) : "r"(addr))

#define MMA(d, a, b) \
    asm volatile("mma.sync.aligned.m16n8k16.row.col.f32.bf16.bf16.f32 " \
                 "{%0,%1,%2,%3}, {%4,%5,%6,%7}, {%8,%9}, {%0,%1,%2,%3};" \
                 : "+f"((d)[0]), "+f"((d)[1]), "+f"((d)[2]), "+f"((d)[3]) \
                 : "r"((a)[0]), "r"((a)[1]), "r"((a)[2]), "r"((a)[3]), \
                   "r"((b)[0]), "r"((b)[1]))

__device__ __forceinline__ uint32_t pack_bf2(float v0, float v1) {
    __nv_bfloat162 t = __float22bfloat162_rn(make_float2(v0, v1));
    uint32_t u;
    memcpy(&u, &t, 4);
    return u;
}
__device__ __forceinline__ void split2(float v0, float v1,
                                       uint32_t& h, uint32_t& l) {
    __nv_bfloat16 h0 = __float2bfloat16(v0);
    __nv_bfloat16 h1 = __float2bfloat16(v1);
    h = pack_bf2(v0, v1);
    l = pack_bf2(v0 - __bfloat162float(h0), v1 - __bfloat162float(h1));
}

// smem plane offsets within a stage (each plane: 128 rows x 64B = 8KB)
#define PL_AH 0
#define PL_AL 8192
#define PL_BH 16384
#define PL_BL 24576
#define STAGE_BYTES 32768
#define SMEM_BYTES 65536

// swizzled byte offset for element (row r, k-elem k) within an 8KB plane:
// rows of 64B (32 bf16); 16B chunk index c = k>>3, chunk ^= (r>>1)&3
__device__ __forceinline__ uint32_t swz(int r, int kc) {
    return (uint32_t)(r * 64 + ((kc ^ ((r >> 1) & 3)) << 4));
}

// ---------------------------------------------------------------------------
// NT GEMM, bf16x3 split precision via mma.sync.m16n8k16.
// C[m,n] = sum_k A[m,k]*B[n,k], A=Ah+Al, B=Bh+Bl (K-major bf16 planes).
// mode 0: Cf fp32 row-major (no bias).
// mode 1: Ch/Cl bf16 planes row-major (+bias).
// mode 2: Ch/Cl bf16 planes transposed per batch -> [b][n][m%LL] (+bias).
// ---------------------------------------------------------------------------
__global__ void __launch_bounds__(256) gemm_mma(
    const __nv_bfloat16* __restrict__ Ah, const __nv_bfloat16* __restrict__ Al,
    const __nv_bfloat16* __restrict__ Bh, const __nv_bfloat16* __restrict__ Bl,
    const float* __restrict__ bias,
    float* __restrict__ Cf,
    __nv_bfloat16* __restrict__ Ch, __nv_bfloat16* __restrict__ Cl,
    int N, int K,
    size_t sAz, size_t sBz, size_t sCz,
    int mode)
{
    extern __shared__ char smem[];
    const uint32_t sbase = smem_u32(smem);
    const int tid  = threadIdx.x;
    const int lane = tid & 31;
    const int warp = tid >> 5;
    const int wm = (warp >> 1) * 32;   // 4 m-warps
    const int wn = (warp & 1) * 64;    // 2 n-warps
    const int m0 = blockIdx.y * 128, n0 = blockIdx.x * 128, bz = blockIdx.z;

    const __nv_bfloat16* pAh = Ah + bz * sAz + (size_t)m0 * K;
    const __nv_bfloat16* pAl = Al + bz * sAz + (size_t)m0 * K;
    const __nv_bfloat16* pBh = Bh + bz * sBz + (size_t)n0 * K;
    const __nv_bfloat16* pBl = Bl + bz * sBz + (size_t)n0 * K;

    float acc[2][8][4];
    #pragma unroll
    for (int i = 0; i < 2; i++)
        #pragma unroll
        for (int j = 0; j < 8; j++)
            #pragma unroll
            for (int c = 0; c < 4; c++) acc[i][j][c] = 0.f;

#define LOAD_STAGE(buf, kt) do { \
    uint32_t so_ = sbase + (buf) * STAGE_BYTES; \
    size_t ko_ = (size_t)(kt) * 32; \
    _Pragma("unroll") \
    for (int i_ = 0; i_ < 2; i_++) { \
        int idx_ = tid + i_ * 256; \
        int r_ = idx_ >> 2, c_ = idx_ & 3; \
        uint32_t d_ = so_ + swz(r_, c_); \
        size_t g_ = (size_t)r_ * K + ko_ + c_ * 8; \
        CP16(d_ + PL_AH, pAh + g_); \
        CP16(d_ + PL_AL, pAl + g_); \
        CP16(d_ + PL_BH, pBh + g_); \
        CP16(d_ + PL_BL, pBl + g_); \
    } \
} while (0)

    const int nk = K >> 5;
    LOAD_STAGE(0, 0);
    CP_COMMIT();

    for (int kt = 0; kt < nk; kt++) {
        if (kt + 1 < nk) LOAD_STAGE((kt + 1) & 1, kt + 1);
        CP_COMMIT();
        CP_WAIT1();
        __syncthreads();

        const uint32_t so = sbase + (kt & 1) * STAGE_BYTES;
        #pragma unroll
        for (int ks = 0; ks < 2; ks++) {
            uint32_t a_h[2][4], a_l[2][4];
            const int kc = ks * 2 + (lane >> 4);
            #pragma unroll
            for (int im = 0; im < 2; im++) {
                int rr = wm + im * 16 + (lane & 7) + ((lane >> 3) & 1) * 8;
                uint32_t ad = so + swz(rr, kc);
                LDSM4(a_h[im][0], a_h[im][1], a_h[im][2], a_h[im][3], ad + PL_AH);
                LDSM4(a_l[im][0], a_l[im][1], a_l[im][2], a_l[im][3], ad + PL_AL);
            }
            uint32_t b_h[8][2], b_l[8][2];
            #pragma unroll
            for (int j4 = 0; j4 < 4; j4++) {
                int rr = wn + j4 * 16 + (lane & 7) + ((lane >> 3) & 1) * 8;
                uint32_t bd = so + swz(rr, kc);
                LDSM4(b_h[2*j4][0], b_h[2*j4+1][0], b_h[2*j4][1], b_h[2*j4+1][1],
                      bd + PL_BH);
                LDSM4(b_l[2*j4][0], b_l[2*j4+1][0], b_l[2*j4][1], b_l[2*j4+1][1],
                      bd + PL_BL);
            }
            #pragma unroll
            for (int im = 0; im < 2; im++)
                #pragma unroll
                for (int j = 0; j < 8; j++) MMA(acc[im][j], a_h[im], b_h[j]);
            #pragma unroll
            for (int im = 0; im < 2; im++)
                #pragma unroll
                for (int j = 0; j < 8; j++) MMA(acc[im][j], a_h[im], b_l[j]);
            #pragma unroll
            for (int im = 0; im < 2; im++)
                #pragma unroll
                for (int j = 0; j < 8; j++) MMA(acc[im][j], a_l[im], b_h[j]);
        }
        __syncthreads();
    }
#undef LOAD_STAGE

    // ---------------- epilogue ----------------
    if (mode == 0) {
        float* base = Cf + bz * sCz;
        #pragma unroll
        for (int im = 0; im < 2; im++) {
            int gm = m0 + wm + im * 16 + (lane >> 2);
            #pragma unroll
            for (int j = 0; j < 8; j++) {
                int gn = n0 + wn + j * 8 + 2 * (lane & 3);
                float2 v0 = make_float2(acc[im][j][0], acc[im][j][1]);
                float2 v1 = make_float2(acc[im][j][2], acc[im][j][3]);
                *reinterpret_cast<float2*>(base + (size_t)gm * N + gn) = v0;
                *reinterpret_cast<float2*>(base + (size_t)(gm + 8) * N + gn) = v1;
            }
        }
    } else if (mode == 1) {
        #pragma unroll
        for (int im = 0; im < 2; im++) {
            int gm = m0 + wm + im * 16 + (lane >> 2);
            #pragma unroll
            for (int j = 0; j < 8; j++) {
                int gn = n0 + wn + j * 8 + 2 * (lane & 3);
                float b0 = bias[gn], b1 = bias[gn + 1];
                uint32_t h, l;
                split2(acc[im][j][0] + b0, acc[im][j][1] + b1, h, l);
                *reinterpret_cast<uint32_t*>(Ch + (size_t)gm * N + gn) = h;
                *reinterpret_cast<uint32_t*>(Cl + (size_t)gm * N + gn) = l;
                split2(acc[im][j][2] + b0, acc[im][j][3] + b1, h, l);
                *reinterpret_cast<uint32_t*>(Ch + (size_t)(gm + 8) * N + gn) = h;
                *reinterpret_cast<uint32_t*>(Cl + (size_t)(gm + 8) * N + gn) = l;
            }
        }
    } else {
        // stage fp32 tile in smem, then write transposed [b][n][l] coalesced
        float* sC = reinterpret_cast<float*>(smem);
        #pragma unroll
        for (int im = 0; im < 2; im++) {
            int rr = wm + im * 16 + (lane >> 2);
            #pragma unroll
            for (int j = 0; j < 8; j++) {
                int cc = wn + j * 8 + 2 * (lane & 3);
                sC[rr * 128 + cc]           = acc[im][j][0];
                sC[rr * 128 + cc + 1]       = acc[im][j][1];
                sC[(rr + 8) * 128 + cc]     = acc[im][j][2];
                sC[(rr + 8) * 128 + cc + 1] = acc[im][j][3];
            }
        }
        __syncthreads();
        const int nl = tid & 127;
        const int mh = tid >> 7;
        const float bv = bias ? bias[n0 + nl] : 0.f;
        const int b  = m0 >> 11;
        const int l0 = (m0 & (LL - 1)) + mh * 64;
        size_t base = ((size_t)b * DD + (n0 + nl)) * (size_t)LL + l0;
        for (int i = 0; i < 64; i += 8) {
            uint32_t hr[4], lr[4];
            #pragma unroll
            for (int p = 0; p < 4; p++) {
                float v0 = sC[(mh * 64 + i + 2 * p)     * 128 + nl] + bv;
                float v1 = sC[(mh * 64 + i + 2 * p + 1) * 128 + nl] + bv;
                split2(v0, v1, hr[p], lr[p]);
            }
            *reinterpret_cast<uint4*>(Ch + base + i) =
                make_uint4(hr[0], hr[1], hr[2], hr[3]);
            *reinterpret_cast<uint4*>(Cl + base + i) =
                make_uint4(lr[0], lr[1], lr[2], lr[3]);
        }
    }
}

// ---------------------------------------------------------------------------
// fp32 -> bf16 hi/lo split (vectorized x4)
// ---------------------------------------------------------------------------
__global__ void __launch_bounds__(256) cvt_split(
    const float* __restrict__ x,
    __nv_bfloat16* __restrict__ h, __nv_bfloat16* __restrict__ lo)
{
    size_t i = (size_t)blockIdx.x * 256 + threadIdx.x;
    float4 v = reinterpret_cast<const float4*>(x)[i];
    uint32_t h0, l0, h1, l1;
    split2(v.x, v.y, h0, l0);
    split2(v.z, v.w, h1, l1);
    reinterpret_cast<uint32_t*>(h)[2 * i + 0]  = h0;
    reinterpret_cast<uint32_t*>(h)[2 * i + 1]  = h1;
    reinterpret_cast<uint32_t*>(lo)[2 * i + 0] = l0;
    reinterpret_cast<uint32_t*>(lo)[2 * i + 1] = l1;
}

// ---------------------------------------------------------------------------
// Column softmax (over axis=1 == queries i, per key column j)
// ---------------------------------------------------------------------------
__global__ void __launch_bounds__(256) colstats_partial()
{
    const int b     = blockIdx.z;
    const int slice = blockIdx.y;
    const int j     = blockIdx.x * 256 + threadIdx.x;
    const float* Sb = g_S + (size_t)b * LL * LL + (size_t)slice * (LL / 8) * LL + j;
    float m = -INFINITY, z = 0.f;
    #pragma unroll 4
    for (int i = 0; i < LL / 8; i++) {
        float s = Sb[(size_t)i * LL];
        if (s > m) { z = z * __expf(m - s) + 1.f; m = s; }
        else       { z += __expf(s - m); }
    }
    const int out = slice * BL + b * LL + j;
    g_pm[out] = m;
    g_pz[out] = z;
}

__global__ void __launch_bounds__(256) colstats_combine()
{
    const int c = blockIdx.x * 256 + threadIdx.x;
    float m = -INFINITY, z = 0.f;
    #pragma unroll
    for (int s = 0; s < 8; s++) {
        float mm = g_pm[s * BL + c];
        float zz = g_pz[s * BL + c];
        if (mm > m) { z = z * __expf(m - mm) + zz; m = mm; }
        else        { z += zz * __expf(mm - m); }
    }
    g_cmax[c]  = m;
    g_crcpz[c] = 1.f / z;
}

// P = exp(S - cmax_j) * rcpz_j, written as bf16 hi/lo planes
__global__ void __launch_bounds__(256) pnorm_bf16()
{
    size_t i4 = (size_t)blockIdx.x * 256 + threadIdx.x;
    size_t e  = i4 * 4;
    int b = (int)(e >> 22);
    int j = (int)(e & (LL - 1));
    float4 s = reinterpret_cast<float4*>(g_S)[i4];
    float4 m4 = *reinterpret_cast<const float4*>(&g_cmax[b * LL + j]);
    float4 z4 = *reinterpret_cast<const float4*>(&g_crcpz[b * LL + j]);
    float p0 = __expf(s.x - m4.x) * z4.x;
    float p1 = __expf(s.y - m4.y) * z4.y;
    float p2 = __expf(s.z - m4.z) * z4.z;
    float p3 = __expf(s.w - m4.w) * z4.w;
    uint32_t h0, l0, h1, l1;
    split2(p0, p1, h0, l0);
    split2(p2, p3, h1, l1);
    reinterpret_cast<uint32_t*>(g_Ph)[2 * i4 + 0] = h0;
    reinterpret_cast<uint32_t*>(g_Ph)[2 * i4 + 1] = h1;
    reinterpret_cast<uint32_t*>(g_Pl)[2 * i4 + 0] = l0;
    reinterpret_cast<uint32_t*>(g_Pl)[2 * i4 + 1] = l1;
}

// ---------------------------------------------------------------------------
extern "C" void kernel_launch(void* const* d_in, const int* in_sizes, int n_in,
                              void* d_out, int out_size)
{
    const float* q  = (const float*)d_in[0];
    const float* k  = (const float*)d_in[1];
    const float* v  = (const float*)d_in[2];
    const float* Wq = (const float*)d_in[3];
    const float* bq = (const float*)d_in[4];
    const float* Wk = (const float*)d_in[5];
    const float* bk = (const float*)d_in[6];
    const float* Wv = (const float*)d_in[7];
    const float* bv = (const float*)d_in[8];
    float* out = (float*)d_out;

    __nv_bfloat16 *qh, *ql, *kh, *kl, *vh, *vl;
    __nv_bfloat16 *Wqh, *Wql, *Wkh, *Wkl, *Wvh, *Wvl;
    __nv_bfloat16 *qph, *qpl, *kph, *kpl, *vpTh, *vpTl, *Ph, *Pl;
    float* S;
    cudaGetSymbolAddress((void**)&qh, g_qh);   cudaGetSymbolAddress((void**)&ql, g_ql);
    cudaGetSymbolAddress((void**)&kh, g_kh);   cudaGetSymbolAddress((void**)&kl, g_kl);
    cudaGetSymbolAddress((void**)&vh, g_vh);   cudaGetSymbolAddress((void**)&vl, g_vl);
    cudaGetSymbolAddress((void**)&Wqh, g_Wqh); cudaGetSymbolAddress((void**)&Wql, g_Wql);
    cudaGetSymbolAddress((void**)&Wkh, g_Wkh); cudaGetSymbolAddress((void**)&Wkl, g_Wkl);
    cudaGetSymbolAddress((void**)&Wvh, g_Wvh); cudaGetSymbolAddress((void**)&Wvl, g_Wvl);
    cudaGetSymbolAddress((void**)&qph, g_qph); cudaGetSymbolAddress((void**)&qpl, g_qpl);
    cudaGetSymbolAddress((void**)&kph, g_kph); cudaGetSymbolAddress((void**)&kpl, g_kpl);
    cudaGetSymbolAddress((void**)&vpTh, g_vpTh); cudaGetSymbolAddress((void**)&vpTl, g_vpTl);
    cudaGetSymbolAddress((void**)&Ph, g_Ph);   cudaGetSymbolAddress((void**)&Pl, g_Pl);
    cudaGetSymbolAddress((void**)&S, g_S);

    cudaFuncSetAttribute(gemm_mma, cudaFuncAttributeMaxDynamicSharedMemorySize,
                         SMEM_BYTES);

    // 0) split fp32 -> bf16 hi/lo
    cvt_split<<<(BL * DD) / 1024, 256>>>(q, qh, ql);
    cvt_split<<<(BL * DD) / 1024, 256>>>(k, kh, kl);
    cvt_split<<<(BL * DD) / 1024, 256>>>(v, vh, vl);
    cvt_split<<<(DD * DD) / 1024, 256>>>(Wq, Wqh, Wql);
    cvt_split<<<(DD * DD) / 1024, 256>>>(Wk, Wkh, Wkl);
    cvt_split<<<(DD * DD) / 1024, 256>>>(Wv, Wvh, Wvl);

    // 1) projections: (BL x D) = in @ W^T + bias
    {
        dim3 gp(DD / 128, BL / 128, 1);
        gemm_mma<<<gp, 256, SMEM_BYTES>>>(qh, ql, Wqh, Wql, bq,
                                          nullptr, qph, qpl,
                                          DD, DD, 0, 0, 0, 1);
        gemm_mma<<<gp, 256, SMEM_BYTES>>>(kh, kl, Wkh, Wkl, bk,
                                          nullptr, kph, kpl,
                                          DD, DD, 0, 0, 0, 1);
        gemm_mma<<<gp, 256, SMEM_BYTES>>>(vh, vl, Wvh, Wvl, bv,
                                          nullptr, vpTh, vpTl,
                                          DD, DD, 0, 0, 0, 2);
    }

    // 2) S[b] = qp[b] @ kp[b]^T
    {
        dim3 gs(LL / 128, LL / 128, BB);
        gemm_mma<<<gs, 256, SMEM_BYTES>>>(qph, qpl, kph, kpl, nullptr,
                                          S, nullptr, nullptr,
                                          LL, DD,
                                          (size_t)LL * DD, (size_t)LL * DD,
                                          (size_t)LL * LL, 0);
    }

    // 3) column softmax stats + normalize into bf16 planes
    {
        dim3 gc(LL / 256, 8, BB);
        colstats_partial<<<gc, 256>>>();
        colstats_combine<<<BL / 256, 256>>>();
        pnorm_bf16<<<(unsigned)((size_t)BB * LL * LL / 1024), 256>>>();
    }

    // 4) out[b] = P[b] @ vp[b]  ==  P @ vpT^T  (NT)
    {
        dim3 go(DD / 128, LL / 128, BB);
        gemm_mma<<<go, 256, SMEM_BYTES>>>(Ph, Pl, vpTh, vpTl, nullptr,
                                          out, nullptr, nullptr,
                                          DD, LL,
                                          (size_t)LL * LL, (size_t)DD * LL,
                                          (size_t)LL * DD, 0);
    }
}

// round 5
// speedup vs baseline: 2.7366x; 1.1039x over previous
#include <cuda_runtime.h>
#include <cuda_bf16.h>
#include <cstdint>
#include <math.h>

#define BB 8
#define LL 2048
#define DD 512
#define BL (BB*LL)

// ---------------------------------------------------------------------------
// Device scratch (static allocations — allowed)
// ---------------------------------------------------------------------------
__device__ __align__(256) __nv_bfloat16 g_Eh[(size_t)BB*LL*LL];   // exp(S) hi
__device__ __align__(256) __nv_bfloat16 g_El[(size_t)BB*LL*LL];   // exp(S) lo
__device__ __align__(256) __nv_bfloat16 g_qh[BL*DD], g_ql[BL*DD];
__device__ __align__(256) __nv_bfloat16 g_kh[BL*DD], g_kl[BL*DD];
__device__ __align__(256) __nv_bfloat16 g_vh[BL*DD], g_vl[BL*DD];
__device__ __align__(256) __nv_bfloat16 g_Wqh[DD*DD], g_Wql[DD*DD];
__device__ __align__(256) __nv_bfloat16 g_Wkh[DD*DD], g_Wkl[DD*DD];
__device__ __align__(256) __nv_bfloat16 g_Wvh[DD*DD], g_Wvl[DD*DD];
__device__ __align__(256) __nv_bfloat16 g_qph[BL*DD], g_qpl[BL*DD];
__device__ __align__(256) __nv_bfloat16 g_kph[BL*DD], g_kpl[BL*DD];
__device__ __align__(256) __nv_bfloat16 g_vpTh[BL*DD], g_vpTl[BL*DD]; // [B][D][L]
__device__ __align__(256) float g_crcpz[BL];
__device__ __align__(256) float g_pz[16*BL];     // per-row-tile column sums

// ---------------------------------------------------------------------------
// Portable PTX helpers (sm_80+ only)
// ---------------------------------------------------------------------------
__device__ __forceinline__ uint32_t smem_u32(const void* p) {
    uint32_t a;
    asm("{ .reg .u64 t; cvta.to.shared.u64 t, %1; cvt.u32.u64 %0, t; }"
        : "=r"(a) : "l"(p));
    return a;
}

#define CP16(dst, src) \
    asm volatile("cp.async.cg.shared.global [%0], [%1], 16;" \
                 :: "r"(dst), "l"(src) : "memory")

#define CP_COMMIT() asm volatile("cp.async.commit_group;" ::: "memory")
#define CP_WAIT1()  asm volatile("cp.async.wait_group 1;" ::: "memory")

#define LDSM4(r0, r1, r2, r3, addr) \
    asm volatile("ldmatrix.sync.aligned.m8n8.x4.shared.b16 {%0,%1,%2,%3}, [%4];" \
                 : "=r"(r0), "=r"(r1), "=r"(r2), "=r"(r3) : "r"(addr))

#define MMA(d, a, b) \
    asm volatile("mma.sync.aligned.m16n8k16.row.col.f32.bf16.bf16.f32 " \
                 "{%0,%1,%2,%3}, {%4,%5,%6,%7}, {%8,%9}, {%0,%1,%2,%3};" \
                 : "+f"((d)[0]), "+f"((d)[1]), "+f"((d)[2]), "+f"((d)[3]) \
                 : "r"((a)[0]), "r"((a)[1]), "r"((a)[2]), "r"((a)[3]), \
                   "r"((b)[0]), "r"((b)[1]))

__device__ __forceinline__ uint32_t pack_bf2(float v0, float v1) {
    __nv_bfloat162 t = __float22bfloat162_rn(make_float2(v0, v1));
    uint32_t u;
    memcpy(&u, &t, 4);
    return u;
}
__device__ __forceinline__ void split2(float v0, float v1,
                                       uint32_t& h, uint32_t& l) {
    __nv_bfloat16 h0 = __float2bfloat16(v0);
    __nv_bfloat16 h1 = __float2bfloat16(v1);
    h = pack_bf2(v0, v1);
    l = pack_bf2(v0 - __bfloat162float(h0), v1 - __bfloat162float(h1));
}

// Fast exp on the FMA pipe: magic-number round + deg-5 2^f poly (rel err ~2e-6)
__device__ __forceinline__ float fast_exp(float x) {
    float y = x * 1.4426950408889634f;
    float t = y + 12582912.f;                       // round-to-nearest via magic
    int   n = __float_as_int(t) - 0x4B400000;
    t -= 12582912.f;
    float f = y - t;                                // f in [-0.5, 0.5]
    float p = 1.3333558146e-3f;
    p = fmaf(p, f, 9.6181291076e-3f);
    p = fmaf(p, f, 5.5504108664e-2f);
    p = fmaf(p, f, 2.4022650696e-1f);
    p = fmaf(p, f, 6.9314718056e-1f);
    p = fmaf(p, f, 1.0f);
    return __int_as_float(__float_as_int(p) + (n << 23));
}

// smem plane offsets within a stage (each plane: 128 rows x 64B = 8KB)
#define PL_AH 0
#define PL_AL 8192
#define PL_BH 16384
#define PL_BL 24576
#define STAGE_BYTES 32768
#define SMEM_BYTES 65536

__device__ __forceinline__ uint32_t swz(int r, int kc) {
    return (uint32_t)(r * 64 + ((kc ^ ((r >> 1) & 3)) << 4));
}

// ---------------------------------------------------------------------------
// NT GEMM, bf16x3 split precision via mma.sync.m16n8k16.
// C[m,n] = sum_k A[m,k]*B[n,k], A=Ah+Al, B=Bh+Bl (K-major bf16 planes).
// mode 0: Cf fp32 row-major (no bias).
// mode 1: Ch/Cl bf16 planes row-major (+bias).
// mode 2: Ch/Cl bf16 planes transposed per batch -> [b][n][m%LL] (+bias).
// mode 3: Ch/Cl = exp(C) bf16 planes row-major + per-tile column sums -> g_pz.
// ---------------------------------------------------------------------------
__global__ void __launch_bounds__(256) gemm_mma(
    const __nv_bfloat16* __restrict__ Ah, const __nv_bfloat16* __restrict__ Al,
    const __nv_bfloat16* __restrict__ Bh, const __nv_bfloat16* __restrict__ Bl,
    const float* __restrict__ bias,
    float* __restrict__ Cf,
    __nv_bfloat16* __restrict__ Ch, __nv_bfloat16* __restrict__ Cl,
    int N, int K,
    size_t sAz, size_t sBz, size_t sCz,
    int mode)
{
    extern __shared__ char smem[];
    const uint32_t sbase = smem_u32(smem);
    const int tid  = threadIdx.x;
    const int lane = tid & 31;
    const int warp = tid >> 5;
    const int wm = (warp >> 1) * 32;   // 4 m-warps
    const int wn = (warp & 1) * 64;    // 2 n-warps
    const int m0 = blockIdx.y * 128, n0 = blockIdx.x * 128, bz = blockIdx.z;

    const __nv_bfloat16* pAh = Ah + bz * sAz + (size_t)m0 * K;
    const __nv_bfloat16* pAl = Al + bz * sAz + (size_t)m0 * K;
    const __nv_bfloat16* pBh = Bh + bz * sBz + (size_t)n0 * K;
    const __nv_bfloat16* pBl = Bl + bz * sBz + (size_t)n0 * K;

    float acc[2][8][4];
    #pragma unroll
    for (int i = 0; i < 2; i++)
        #pragma unroll
        for (int j = 0; j < 8; j++)
            #pragma unroll
            for (int c = 0; c < 4; c++) acc[i][j][c] = 0.f;

#define LOAD_STAGE(buf, kt) do { \
    uint32_t so_ = sbase + (buf) * STAGE_BYTES; \
    size_t ko_ = (size_t)(kt) * 32; \
    _Pragma("unroll") \
    for (int i_ = 0; i_ < 2; i_++) { \
        int idx_ = tid + i_ * 256; \
        int r_ = idx_ >> 2, c_ = idx_ & 3; \
        uint32_t d_ = so_ + swz(r_, c_); \
        size_t g_ = (size_t)r_ * K + ko_ + c_ * 8; \
        CP16(d_ + PL_AH, pAh + g_); \
        CP16(d_ + PL_AL, pAl + g_); \
        CP16(d_ + PL_BH, pBh + g_); \
        CP16(d_ + PL_BL, pBl + g_); \
    } \
} while (0)

    const int nk = K >> 5;
    LOAD_STAGE(0, 0);
    CP_COMMIT();

    for (int kt = 0; kt < nk; kt++) {
        if (kt + 1 < nk) LOAD_STAGE((kt + 1) & 1, kt + 1);
        CP_COMMIT();
        CP_WAIT1();
        __syncthreads();

        const uint32_t so = sbase + (kt & 1) * STAGE_BYTES;
        #pragma unroll
        for (int ks = 0; ks < 2; ks++) {
            uint32_t a_h[2][4], a_l[2][4];
            const int kc = ks * 2 + (lane >> 4);
            #pragma unroll
            for (int im = 0; im < 2; im++) {
                int rr = wm + im * 16 + (lane & 7) + ((lane >> 3) & 1) * 8;
                uint32_t ad = so + swz(rr, kc);
                LDSM4(a_h[im][0], a_h[im][1], a_h[im][2], a_h[im][3], ad + PL_AH);
                LDSM4(a_l[im][0], a_l[im][1], a_l[im][2], a_l[im][3], ad + PL_AL);
            }
            uint32_t b_h[8][2], b_l[8][2];
            #pragma unroll
            for (int j4 = 0; j4 < 4; j4++) {
                int rr = wn + j4 * 16 + (lane & 7) + ((lane >> 3) & 1) * 8;
                uint32_t bd = so + swz(rr, kc);
                LDSM4(b_h[2*j4][0], b_h[2*j4+1][0], b_h[2*j4][1], b_h[2*j4+1][1],
                      bd + PL_BH);
                LDSM4(b_l[2*j4][0], b_l[2*j4+1][0], b_l[2*j4][1], b_l[2*j4+1][1],
                      bd + PL_BL);
            }
            #pragma unroll
            for (int im = 0; im < 2; im++)
                #pragma unroll
                for (int j = 0; j < 8; j++) MMA(acc[im][j], a_h[im], b_h[j]);
            #pragma unroll
            for (int im = 0; im < 2; im++)
                #pragma unroll
                for (int j = 0; j < 8; j++) MMA(acc[im][j], a_h[im], b_l[j]);
            #pragma unroll
            for (int im = 0; im < 2; im++)
                #pragma unroll
                for (int j = 0; j < 8; j++) MMA(acc[im][j], a_l[im], b_h[j]);
        }
        __syncthreads();
    }
#undef LOAD_STAGE

    // ---------------- epilogue ----------------
    // Batch-offset output bases (THE R4 BUG: mode 3 was missing bz*sCz)
    __nv_bfloat16* pCh = Ch + bz * sCz;
    __nv_bfloat16* pCl = Cl + bz * sCz;

    if (mode == 0) {
        float* base = Cf + bz * sCz;
        #pragma unroll
        for (int im = 0; im < 2; im++) {
            int gm = m0 + wm + im * 16 + (lane >> 2);
            #pragma unroll
            for (int j = 0; j < 8; j++) {
                int gn = n0 + wn + j * 8 + 2 * (lane & 3);
                float2 v0 = make_float2(acc[im][j][0], acc[im][j][1]);
                float2 v1 = make_float2(acc[im][j][2], acc[im][j][3]);
                *reinterpret_cast<float2*>(base + (size_t)gm * N + gn) = v0;
                *reinterpret_cast<float2*>(base + (size_t)(gm + 8) * N + gn) = v1;
            }
        }
    } else if (mode == 1) {
        #pragma unroll
        for (int im = 0; im < 2; im++) {
            int gm = m0 + wm + im * 16 + (lane >> 2);
            #pragma unroll
            for (int j = 0; j < 8; j++) {
                int gn = n0 + wn + j * 8 + 2 * (lane & 3);
                float b0 = bias[gn], b1 = bias[gn + 1];
                uint32_t h, l;
                split2(acc[im][j][0] + b0, acc[im][j][1] + b1, h, l);
                *reinterpret_cast<uint32_t*>(pCh + (size_t)gm * N + gn) = h;
                *reinterpret_cast<uint32_t*>(pCl + (size_t)gm * N + gn) = l;
                split2(acc[im][j][2] + b0, acc[im][j][3] + b1, h, l);
                *reinterpret_cast<uint32_t*>(pCh + (size_t)(gm + 8) * N + gn) = h;
                *reinterpret_cast<uint32_t*>(pCl + (size_t)(gm + 8) * N + gn) = l;
            }
        }
    } else if (mode == 2) {
        // stage fp32 tile in smem, then write transposed [b][n][l] coalesced
        float* sC = reinterpret_cast<float*>(smem);
        #pragma unroll
        for (int im = 0; im < 2; im++) {
            int rr = wm + im * 16 + (lane >> 2);
            #pragma unroll
            for (int j = 0; j < 8; j++) {
                int cc = wn + j * 8 + 2 * (lane & 3);
                sC[rr * 128 + cc]           = acc[im][j][0];
                sC[rr * 128 + cc + 1]       = acc[im][j][1];
                sC[(rr + 8) * 128 + cc]     = acc[im][j][2];
                sC[(rr + 8) * 128 + cc + 1] = acc[im][j][3];
            }
        }
        __syncthreads();
        const int nl = tid & 127;
        const int mh = tid >> 7;
        const float bv = bias ? bias[n0 + nl] : 0.f;
        const int b  = m0 >> 11;
        const int l0 = (m0 & (LL - 1)) + mh * 64;
        size_t base = ((size_t)b * DD + (n0 + nl)) * (size_t)LL + l0;
        for (int i = 0; i < 64; i += 8) {
            uint32_t hr[4], lr[4];
            #pragma unroll
            for (int p = 0; p < 4; p++) {
                float v0 = sC[(mh * 64 + i + 2 * p)     * 128 + nl] + bv;
                float v1 = sC[(mh * 64 + i + 2 * p + 1) * 128 + nl] + bv;
                split2(v0, v1, hr[p], lr[p]);
            }
            *reinterpret_cast<uint4*>(Ch + base + i) =
                make_uint4(hr[0], hr[1], hr[2], hr[3]);
            *reinterpret_cast<uint4*>(Cl + base + i) =
                make_uint4(lr[0], lr[1], lr[2], lr[3]);
        }
    } else {
        // mode 3: E = exp(S), store bf16 hi/lo planes + per-tile column sums
        float cs[8][2];
        #pragma unroll
        for (int j = 0; j < 8; j++) { cs[j][0] = 0.f; cs[j][1] = 0.f; }
        #pragma unroll
        for (int im = 0; im < 2; im++) {
            int gm = m0 + wm + im * 16 + (lane >> 2);
            #pragma unroll
            for (int j = 0; j < 8; j++) {
                int gn = n0 + wn + j * 8 + 2 * (lane & 3);
                float e0 = fast_exp(acc[im][j][0]);
                float e1 = fast_exp(acc[im][j][1]);
                float e2 = fast_exp(acc[im][j][2]);
                float e3 = fast_exp(acc[im][j][3]);
                uint32_t h, l;
                split2(e0, e1, h, l);
                *reinterpret_cast<uint32_t*>(pCh + (size_t)gm * N + gn) = h;
                *reinterpret_cast<uint32_t*>(pCl + (size_t)gm * N + gn) = l;
                split2(e2, e3, h, l);
                *reinterpret_cast<uint32_t*>(pCh + (size_t)(gm + 8) * N + gn) = h;
                *reinterpret_cast<uint32_t*>(pCl + (size_t)(gm + 8) * N + gn) = l;
                cs[j][0] += e0 + e2;
                cs[j][1] += e1 + e3;
            }
        }
        // reduce over lanes with same (lane&3): bits 2..4
        #pragma unroll
        for (int j = 0; j < 8; j++) {
            #pragma unroll
            for (int off = 4; off <= 16; off <<= 1) {
                cs[j][0] += __shfl_xor_sync(0xffffffffu, cs[j][0], off);
                cs[j][1] += __shfl_xor_sync(0xffffffffu, cs[j][1], off);
            }
        }
        float* sPart = reinterpret_cast<float*>(smem);
        if (lane < 4) {
            int mwarp = warp >> 1;
            #pragma unroll
            for (int j = 0; j < 8; j++) {
                int col = wn + j * 8 + 2 * (lane & 3);
                sPart[mwarp * 128 + col]     = cs[j][0];
                sPart[mwarp * 128 + col + 1] = cs[j][1];
            }
        }
        __syncthreads();
        if (tid < 128) {
            float tot = sPart[tid] + sPart[128 + tid] +
                        sPart[256 + tid] + sPart[384 + tid];
            g_pz[(size_t)blockIdx.y * BL + bz * LL + n0 + tid] = tot;
        }
    }
}

// ---------------------------------------------------------------------------
// fp32 -> bf16 hi/lo split (vectorized x4)
// ---------------------------------------------------------------------------
__global__ void __launch_bounds__(256) cvt_split(
    const float* __restrict__ x,
    __nv_bfloat16* __restrict__ h, __nv_bfloat16* __restrict__ lo)
{
    size_t i = (size_t)blockIdx.x * 256 + threadIdx.x;
    float4 v = reinterpret_cast<const float4*>(x)[i];
    uint32_t h0, l0, h1, l1;
    split2(v.x, v.y, h0, l0);
    split2(v.z, v.w, h1, l1);
    reinterpret_cast<uint32_t*>(h)[2 * i + 0]  = h0;
    reinterpret_cast<uint32_t*>(h)[2 * i + 1]  = h1;
    reinterpret_cast<uint32_t*>(lo)[2 * i + 0] = l0;
    reinterpret_cast<uint32_t*>(lo)[2 * i + 1] = l1;
}

// rz[b,j] = 1 / sum over 16 row-tiles of partial column sums
__global__ void __launch_bounds__(256) colsum_combine()
{
    const int c = blockIdx.x * 256 + threadIdx.x;
    float z = 0.f;
    #pragma unroll
    for (int s = 0; s < 16; s++) z += g_pz[(size_t)s * BL + c];
    g_crcpz[c] = 1.f / z;
}

// vpT[b][d][l] *= rz[b][l], in place on bf16 hi/lo planes
__global__ void __launch_bounds__(256) scale_vpT()
{
    size_t idx = (size_t)blockIdx.x * 256 + threadIdx.x;   // per 8 elems
    size_t e0  = idx * 8;
    int l   = (int)(e0 & (LL - 1));
    int row = (int)(e0 >> 11);         // b*DD + d
    int b   = row >> 9;
    uint4 hv = reinterpret_cast<uint4*>(g_vpTh)[idx];
    uint4 lv = reinterpret_cast<uint4*>(g_vpTl)[idx];
    const float* rz = &g_crcpz[b * LL + l];
    uint32_t hw[4] = {hv.x, hv.y, hv.z, hv.w};
    uint32_t lw[4] = {lv.x, lv.y, lv.z, lv.w};
    #pragma unroll
    for (int p = 0; p < 4; p++) {
        __nv_bfloat162 hh = *reinterpret_cast<__nv_bfloat162*>(&hw[p]);
        __nv_bfloat162 ll = *reinterpret_cast<__nv_bfloat162*>(&lw[p]);
        float v0 = (__bfloat162float(hh.x) + __bfloat162float(ll.x)) * rz[2 * p];
        float v1 = (__bfloat162float(hh.y) + __bfloat162float(ll.y)) * rz[2 * p + 1];
        split2(v0, v1, hw[p], lw[p]);
    }
    reinterpret_cast<uint4*>(g_vpTh)[idx] = make_uint4(hw[0], hw[1], hw[2], hw[3]);
    reinterpret_cast<uint4*>(g_vpTl)[idx] = make_uint4(lw[0], lw[1], lw[2], lw[3]);
}

// ---------------------------------------------------------------------------
extern "C" void kernel_launch(void* const* d_in, const int* in_sizes, int n_in,
                              void* d_out, int out_size)
{
    const float* q  = (const float*)d_in[0];
    const float* k  = (const float*)d_in[1];
    const float* v  = (const float*)d_in[2];
    const float* Wq = (const float*)d_in[3];
    const float* bq = (const float*)d_in[4];
    const float* Wk = (const float*)d_in[5];
    const float* bk = (const float*)d_in[6];
    const float* Wv = (const float*)d_in[7];
    const float* bv = (const float*)d_in[8];
    float* out = (float*)d_out;

    __nv_bfloat16 *qh, *ql, *kh, *kl, *vh, *vl;
    __nv_bfloat16 *Wqh, *Wql, *Wkh, *Wkl, *Wvh, *Wvl;
    __nv_bfloat16 *qph, *qpl, *kph, *kpl, *vpTh, *vpTl, *Eh, *El;
    cudaGetSymbolAddress((void**)&qh, g_qh);   cudaGetSymbolAddress((void**)&ql, g_ql);
    cudaGetSymbolAddress((void**)&kh, g_kh);   cudaGetSymbolAddress((void**)&kl, g_kl);
    cudaGetSymbolAddress((void**)&vh, g_vh);   cudaGetSymbolAddress((void**)&vl, g_vl);
    cudaGetSymbolAddress((void**)&Wqh, g_Wqh); cudaGetSymbolAddress((void**)&Wql, g_Wql);
    cudaGetSymbolAddress((void**)&Wkh, g_Wkh); cudaGetSymbolAddress((void**)&Wkl, g_Wkl);
    cudaGetSymbolAddress((void**)&Wvh, g_Wvh); cudaGetSymbolAddress((void**)&Wvl, g_Wvl);
    cudaGetSymbolAddress((void**)&qph, g_qph); cudaGetSymbolAddress((void**)&qpl, g_qpl);
    cudaGetSymbolAddress((void**)&kph, g_kph); cudaGetSymbolAddress((void**)&kpl, g_kpl);
    cudaGetSymbolAddress((void**)&vpTh, g_vpTh); cudaGetSymbolAddress((void**)&vpTl, g_vpTl);
    cudaGetSymbolAddress((void**)&Eh, g_Eh);   cudaGetSymbolAddress((void**)&El, g_El);

    cudaFuncSetAttribute(gemm_mma, cudaFuncAttributeMaxDynamicSharedMemorySize,
                         SMEM_BYTES);

    // 0) split fp32 -> bf16 hi/lo
    cvt_split<<<(BL * DD) / 1024, 256>>>(q, qh, ql);
    cvt_split<<<(BL * DD) / 1024, 256>>>(k, kh, kl);
    cvt_split<<<(BL * DD) / 1024, 256>>>(v, vh, vl);
    cvt_split<<<(DD * DD) / 1024, 256>>>(Wq, Wqh, Wql);
    cvt_split<<<(DD * DD) / 1024, 256>>>(Wk, Wkh, Wkl);
    cvt_split<<<(DD * DD) / 1024, 256>>>(Wv, Wvh, Wvl);

    // 1) projections: (BL x D) = in @ W^T + bias
    {
        dim3 gp(DD / 128, BL / 128, 1);
        gemm_mma<<<gp, 256, SMEM_BYTES>>>(qh, ql, Wqh, Wql, bq,
                                          nullptr, qph, qpl,
                                          DD, DD, 0, 0, 0, 1);
        gemm_mma<<<gp, 256, SMEM_BYTES>>>(kh, kl, Wkh, Wkl, bk,
                                          nullptr, kph, kpl,
                                          DD, DD, 0, 0, 0, 1);
        gemm_mma<<<gp, 256, SMEM_BYTES>>>(vh, vl, Wvh, Wvl, bv,
                                          nullptr, vpTh, vpTl,
                                          DD, DD, 0, 0, 0, 2);
    }

    // 2) E[b] = exp(qp[b] @ kp[b]^T) as bf16 planes + column sums (fused)
    {
        dim3 gs(LL / 128, LL / 128, BB);
        gemm_mma<<<gs, 256, SMEM_BYTES>>>(qph, qpl, kph, kpl, nullptr,
                                          nullptr, Eh, El,
                                          LL, DD,
                                          (size_t)LL * DD, (size_t)LL * DD,
                                          (size_t)LL * LL, 3);
    }

    // 3) rz = 1/colsum; fold into vpT
    colsum_combine<<<BL / 256, 256>>>();
    scale_vpT<<<(BL * DD) / (8 * 256), 256>>>();

    // 4) out[b] = E[b] @ vpT'[b]^T  (NT)
    {
        dim3 go(DD / 128, LL / 128, BB);
        gemm_mma<<<go, 256, SMEM_BYTES>>>(Eh, El, vpTh, vpTl, nullptr,
                                          out, nullptr, nullptr,
                                          DD, LL,
                                          (size_t)LL * LL, (size_t)DD * LL,
                                          (size_t)LL * DD, 0);
    }
}